// round 4
// baseline (speedup 1.0000x reference)
#include <cuda_runtime.h>

#define NTOK 25
#define XS  132    // xs row stride (floats), float4-aligned
#define QKS 388    // qk row stride (floats)
#define WSS 68     // ws row stride (floats): 64 k + 4 pad -> conflict-free LDS.128

typedef unsigned long long u64;

// Precomputed combined (relative-position bias + window mask) per (window, head, i, j)
__device__ float g_bias[64 * 4 * 25 * 25];

__global__ void bias_kernel(const float* __restrict__ mask, const int* __restrict__ ids_keep,
                            const float* __restrict__ bias_table, const int* __restrict__ rel_index) {
    int w = blockIdx.x;
    __shared__ int ids[NTOK];
    if (threadIdx.x < NTOK) ids[threadIdx.x] = ids_keep[w * NTOK + threadIdx.x];
    __syncthreads();
    for (int e = threadIdx.x; e < 4 * NTOK * NTOK; e += blockDim.x) {
        int h = e / (NTOK * NTOK);
        int r = e % (NTOK * NTOK);
        int i = r / NTOK, j = r % NTOK;
        int ia = ids[i], ja = ids[j];
        int rel = rel_index[ia * 49 + ja];
        g_bias[(w * 4 + h) * 625 + r] = bias_table[rel * 4 + h] + mask[(w * 49 + ia) * 49 + ja];
    }
}

__device__ __forceinline__ void ffma2(u64& acc, u64 a, u64 b) {
    asm("fma.rn.f32x2 %0, %1, %2, %0;" : "+l"(acc) : "l"(a), "l"(b));
}
__device__ __forceinline__ float fsum2(u64 v) {
    return __uint_as_float((unsigned)v) + __uint_as_float((unsigned)(v >> 32));
}
__device__ __forceinline__ u64 dup(float x) {
    u64 r; unsigned bb = __float_as_uint(x);
    asm("mov.b64 %0, {%1, %1};" : "=l"(r) : "r"(bb));
    return r;
}

__global__ __launch_bounds__(256, 2) void attn_kernel(
    const float* __restrict__ x,
    const float* __restrict__ qkv_w, const float* __restrict__ qkv_b,
    const float* __restrict__ proj_w, const float* __restrict__ proj_b,
    float* __restrict__ out) {
    extern __shared__ float smem[];
    float* xs = smem;                   // 25 * 132  (input, later attention output)
    float* qk = smem + NTOK * XS;       // 25 * 388  (q | k | v per token)
    float* ws = qk + NTOK * QKS;        // 128 * 68  (64-wide K chunk of weights)

    int b = blockIdx.x;
    int tid = threadIdx.x;

    // ---- Stage 1: x[b] (25 x 128) -> smem ----
    const float* xb = x + (size_t)b * (NTOK * 128);
    for (int idx = tid; idx < NTOK * 128; idx += 256)
        xs[(idx >> 7) * XS + (idx & 127)] = xb[idx];
    __syncthreads();

    // GEMM thread tiling: 64 col-groups (cols cg, cg+64) x 4 token groups (7,6,6,6)
    int cg = tid & 63;
    int tg = tid >> 6;
    int t0 = tg ? (7 + 6 * (tg - 1)) : 0;
    int nt = tg ? 6 : 7;

    // weight staging mapping: each thread copies 8 float4 of one column's half-row
    int sc = tid & 127;
    int sq = (tid >> 7) * 8;

    // ---- Stage 2: qkv = x @ qkv_w.T + qkv_b ----
    for (int cc = 0; cc < 3; cc++) {
        u64 acc0[7], acc1[7];
#pragma unroll
        for (int u = 0; u < 7; u++) { acc0[u] = 0ull; acc1[u] = 0ull; }
        for (int half = 0; half < 2; half++) {
            const float* wsrc = qkv_w + (size_t)(cc * 128 + sc) * 128 + half * 64;
#pragma unroll
            for (int j = 0; j < 8; j++)
                *(float4*)&ws[sc * WSS + (sq + j) * 4] = *(const float4*)&wsrc[(sq + j) * 4];
            __syncthreads();
#pragma unroll
            for (int kq = 0; kq < 16; kq++) {
                ulonglong2 w0 = *(const ulonglong2*)&ws[cg * WSS + kq * 4];
                ulonglong2 w1 = *(const ulonglong2*)&ws[(cg + 64) * WSS + kq * 4];
#pragma unroll
                for (int u = 0; u < 7; u++) {
                    if (u < nt) {
                        ulonglong2 xv = *(const ulonglong2*)&xs[(t0 + u) * XS + half * 64 + kq * 4];
                        ffma2(acc0[u], w0.x, xv.x);
                        ffma2(acc0[u], w0.y, xv.y);
                        ffma2(acc1[u], w1.x, xv.x);
                        ffma2(acc1[u], w1.y, xv.y);
                    }
                }
            }
            __syncthreads();
        }
        float b0 = qkv_b[cc * 128 + cg];
        float b1 = qkv_b[cc * 128 + cg + 64];
        for (int u = 0; u < nt; u++) {
            qk[(t0 + u) * QKS + cc * 128 + cg]      = fsum2(acc0[u]) + b0;
            qk[(t0 + u) * QKS + cc * 128 + cg + 64] = fsum2(acc1[u]) + b1;
        }
    }
    __syncthreads();

    // ---- Stage 3: attention (100 threads: one per (head, query-row)) ----
    const float scale = 0.17677669529663687f;  // 32^-0.5 (applied post-dot)
    if (tid < 100) {
        int h = tid / 25, i = tid - h * 25;
        const float* qrow = qk + i * QKS + h * 32;
        u64 qv[16];
#pragma unroll
        for (int q = 0; q < 8; q++) {
            int qq = (q + 2 * h) & 7;  // per-head 16B rotation: decorrelates banks across heads
            ulonglong2 t = *(const ulonglong2*)&qrow[qq * 4];
            qv[2 * q] = t.x; qv[2 * q + 1] = t.y;
        }
        const float* gb = g_bias + (((b & 63) * 4 + h) * 25 + i) * 25;
        float s[25];
        float m = -1e30f;
        for (int j = 0; j < 25; j++) {
            const float* krow = qk + j * QKS + 128 + h * 32;
            u64 acc = 0ull;
#pragma unroll
            for (int q = 0; q < 8; q++) {
                int qq = (q + 2 * h) & 7;
                ulonglong2 t = *(const ulonglong2*)&krow[qq * 4];
                ffma2(acc, qv[2 * q], t.x);
                ffma2(acc, qv[2 * q + 1], t.y);
            }
            float sv = fsum2(acc) * scale + gb[j];
            s[j] = sv;
            m = fmaxf(m, sv);
        }
        float sum = 0.f;
        for (int j = 0; j < 25; j++) { s[j] = __expf(s[j] - m); sum += s[j]; }
        float inv = 1.f / sum;
        u64 o[16];
#pragma unroll
        for (int q = 0; q < 16; q++) o[q] = 0ull;
        for (int j = 0; j < 25; j++) {
            u64 pp = dup(s[j] * inv);
            const float* vrow = qk + j * QKS + 256 + h * 32;
#pragma unroll
            for (int q = 0; q < 8; q++) {
                int qq = (q + 2 * h) & 7;
                ulonglong2 t = *(const ulonglong2*)&vrow[qq * 4];
                ffma2(o[2 * q], pp, t.x);
                ffma2(o[2 * q + 1], pp, t.y);
            }
        }
        float* orow = xs + i * XS + h * 32;
#pragma unroll
        for (int q = 0; q < 8; q++) {
            int qq = (q + 2 * h) & 7;
            ulonglong2 t;
            t.x = o[2 * q]; t.y = o[2 * q + 1];
            *(ulonglong2*)&orow[qq * 4] = t;
        }
    }
    __syncthreads();

    // ---- Stage 4: out = attn_out @ proj_w.T + proj_b ----
    {
        u64 acc0[7], acc1[7];
#pragma unroll
        for (int u = 0; u < 7; u++) { acc0[u] = 0ull; acc1[u] = 0ull; }
        for (int half = 0; half < 2; half++) {
            const float* wsrc = proj_w + (size_t)sc * 128 + half * 64;
#pragma unroll
            for (int j = 0; j < 8; j++)
                *(float4*)&ws[sc * WSS + (sq + j) * 4] = *(const float4*)&wsrc[(sq + j) * 4];
            __syncthreads();
#pragma unroll
            for (int kq = 0; kq < 16; kq++) {
                ulonglong2 w0 = *(const ulonglong2*)&ws[cg * WSS + kq * 4];
                ulonglong2 w1 = *(const ulonglong2*)&ws[(cg + 64) * WSS + kq * 4];
#pragma unroll
                for (int u = 0; u < 7; u++) {
                    if (u < nt) {
                        ulonglong2 xv = *(const ulonglong2*)&xs[(t0 + u) * XS + half * 64 + kq * 4];
                        ffma2(acc0[u], w0.x, xv.x);
                        ffma2(acc0[u], w0.y, xv.y);
                        ffma2(acc1[u], w1.x, xv.x);
                        ffma2(acc1[u], w1.y, xv.y);
                    }
                }
            }
            __syncthreads();
        }
        float b0 = proj_b[cg], b1 = proj_b[cg + 64];
        float* ob = out + (size_t)b * (NTOK * 128);
        for (int u = 0; u < nt; u++) {
            ob[(t0 + u) * 128 + cg]      = fsum2(acc0[u]) + b0;
            ob[(t0 + u) * 128 + cg + 64] = fsum2(acc1[u]) + b1;
        }
    }
}

extern "C" void kernel_launch(void* const* d_in, const int* in_sizes, int n_in,
                              void* d_out, int out_size) {
    const float* x          = (const float*)d_in[0];
    const float* mask       = (const float*)d_in[1];
    const int*   ids_keep   = (const int*)d_in[2];
    const float* qkv_w      = (const float*)d_in[3];
    const float* qkv_b      = (const float*)d_in[4];
    const float* proj_w     = (const float*)d_in[5];
    const float* proj_b     = (const float*)d_in[6];
    const float* bias_table = (const float*)d_in[7];
    const int*   rel_index  = (const int*)d_in[8];
    float* out = (float*)d_out;

    bias_kernel<<<64, 256>>>(mask, ids_keep, bias_table, rel_index);

    size_t smem = (size_t)(NTOK * XS + NTOK * QKS + 128 * WSS) * sizeof(float);
    cudaFuncSetAttribute(attn_kernel, cudaFuncAttributeMaxDynamicSharedMemorySize, (int)smem);
    attn_kernel<<<4096, 256, smem>>>(x, qkv_w, qkv_b, proj_w, proj_b, out);
}

// round 7
// speedup vs baseline: 3.1677x; 3.1677x over previous
#include <cuda_runtime.h>
#include <cuda_bf16.h>

typedef unsigned int u32;
typedef unsigned long long u64;
#define QKS 388

__device__ float g_bias[64 * 4 * 625];
__device__ float g_qkv[102400ull * 384];
__device__ __nv_bfloat16 g_ao_hi[102400ull * 128];
__device__ __nv_bfloat16 g_ao_lo[102400ull * 128];

__device__ __forceinline__ u32 smem_u32(const void* p) {
    u32 a;
    asm("{ .reg .u64 t; cvta.to.shared.u64 t, %1; cvt.u32.u64 %0, t; }" : "=r"(a) : "l"(p));
    return a;
}
__device__ __forceinline__ void ldsm4(u32* r, u32 a) {
    asm volatile("ldmatrix.sync.aligned.m8n8.x4.shared.b16 {%0,%1,%2,%3}, [%4];"
                 : "=r"(r[0]), "=r"(r[1]), "=r"(r[2]), "=r"(r[3]) : "r"(a));
}
__device__ __forceinline__ void mma16816(float* c, const u32* a, u32 b0, u32 b1) {
    asm volatile("mma.sync.aligned.m16n8k16.row.col.f32.bf16.bf16.f32 "
                 "{%0,%1,%2,%3},{%4,%5,%6,%7},{%8,%9},{%0,%1,%2,%3};"
                 : "+f"(c[0]), "+f"(c[1]), "+f"(c[2]), "+f"(c[3])
                 : "r"(a[0]), "r"(a[1]), "r"(a[2]), "r"(a[3]), "r"(b0), "r"(b1));
}
__device__ __forceinline__ void ffma2(u64& acc, u64 a, u64 b) {
    asm("fma.rn.f32x2 %0, %1, %2, %0;" : "+l"(acc) : "l"(a), "l"(b));
}
__device__ __forceinline__ float fsum2(u64 v) {
    return __uint_as_float((u32)v) + __uint_as_float((u32)(v >> 32));
}
__device__ __forceinline__ u64 dup(float x) {
    u64 r; u32 bb = __float_as_uint(x);
    asm("mov.b64 %0, {%1, %1};" : "=l"(r) : "r"(bb));
    return r;
}

struct alignas(16) BF8 { __nv_bfloat16 v[8]; };
__device__ __forceinline__ void split8(const float* v, BF8& hb, BF8& lb) {
#pragma unroll
    for (int q = 0; q < 8; q++) {
        __nv_bfloat16 h = __float2bfloat16(v[q]);
        hb.v[q] = h;
        lb.v[q] = __float2bfloat16(v[q] - __bfloat162float(h));
    }
}

__global__ void bias_kernel(const float* __restrict__ mask, const int* __restrict__ ids_keep,
                            const float* __restrict__ bias_table, const int* __restrict__ rel_index) {
    int w = blockIdx.x;
    __shared__ int ids[25];
    if (threadIdx.x < 25) ids[threadIdx.x] = ids_keep[w * 25 + threadIdx.x];
    __syncthreads();
    for (int e = threadIdx.x; e < 4 * 625; e += blockDim.x) {
        int h = e / 625, r = e % 625;
        int ia = ids[r / 25], ja = ids[r % 25];
        g_bias[(w * 4 + h) * 625 + r] =
            bias_table[rel_index[ia * 49 + ja] * 4 + h] + mask[(w * 49 + ia) * 49 + ja];
    }
}

// C[M,N] = A[M,128] @ W[N,128]^T + bias.  MODE 0: A fp32 (split in-kernel) -> g_qkv.
// MODE 1: A pre-split bf16 (g_ao_hi/lo) -> C.
template <int MODE>
__global__ __launch_bounds__(256) void gemm_kernel(
    const float* __restrict__ Afp, const float* __restrict__ W,
    const float* __restrict__ bias, float* __restrict__ C, int ldn) {
    extern __shared__ char smx[];
    __nv_bfloat16* a_hi = (__nv_bfloat16*)smx;
    __nv_bfloat16* a_lo = a_hi + 8192;
    __nv_bfloat16* b_hi = a_lo + 8192;
    __nv_bfloat16* b_lo = b_hi + 8192;
    const int tid = threadIdx.x, lane = tid & 31, wid = tid >> 5;
    const int warp_m = wid & 1, warp_n = wid >> 1;
    const int row0 = blockIdx.x * 128, col0 = blockIdx.y * 128;
    const u32 AHI = smem_u32(a_hi), ALO = smem_u32(a_lo);
    const u32 BHI = smem_u32(b_hi), BLO = smem_u32(b_lo);

    float acc[4][4][4];
#pragma unroll
    for (int a = 0; a < 4; a++)
#pragma unroll
        for (int b = 0; b < 4; b++)
#pragma unroll
            for (int c = 0; c < 4; c++) acc[a][b][c] = 0.f;

    for (int kc0 = 0; kc0 < 128; kc0 += 64) {
#pragma unroll
        for (int i = tid; i < 1024; i += 256) {
            int r = i >> 3, c = i & 7;
            int off = ((r << 3) + (c ^ (r & 7))) << 3;
            if (MODE == 0) {
                const float* s = Afp + (size_t)(row0 + r) * 128 + kc0 + c * 8;
                float4 f0 = *(const float4*)s, f1 = *(const float4*)(s + 4);
                float v[8] = {f0.x, f0.y, f0.z, f0.w, f1.x, f1.y, f1.z, f1.w};
                BF8 hb, lb; split8(v, hb, lb);
                *(uint4*)&a_hi[off] = *(uint4*)&hb;
                *(uint4*)&a_lo[off] = *(uint4*)&lb;
            } else {
                size_t s = (size_t)(row0 + r) * 128 + kc0 + c * 8;
                *(uint4*)&a_hi[off] = *(const uint4*)&g_ao_hi[s];
                *(uint4*)&a_lo[off] = *(const uint4*)&g_ao_lo[s];
            }
            const float* ws = W + (size_t)(col0 + r) * 128 + kc0 + c * 8;
            float4 g0 = *(const float4*)ws, g1 = *(const float4*)(ws + 4);
            float u[8] = {g0.x, g0.y, g0.z, g0.w, g1.x, g1.y, g1.z, g1.w};
            BF8 hb2, lb2; split8(u, hb2, lb2);
            *(uint4*)&b_hi[off] = *(uint4*)&hb2;
            *(uint4*)&b_lo[off] = *(uint4*)&lb2;
        }
        __syncthreads();
#pragma unroll
        for (int ks = 0; ks < 4; ks++) {
            u32 ah[4][4], al[4][4], bh[2][4], bl[2][4];
#pragma unroll
            for (int mf = 0; mf < 4; mf++) {
                int row = warp_m * 64 + mf * 16 + (lane & 15);
                u32 boff = row * 128 + (((2 * ks + (lane >> 4)) ^ (row & 7)) << 4);
                ldsm4(ah[mf], AHI + boff);
                ldsm4(al[mf], ALO + boff);
            }
#pragma unroll
            for (int nf2 = 0; nf2 < 2; nf2++) {
                int row = warp_n * 32 + nf2 * 16 + ((lane >> 4) << 3) + (lane & 7);
                u32 boff = row * 128 + (((2 * ks + ((lane >> 3) & 1)) ^ (row & 7)) << 4);
                ldsm4(bh[nf2], BHI + boff);
                ldsm4(bl[nf2], BLO + boff);
            }
#pragma unroll
            for (int mf = 0; mf < 4; mf++)
#pragma unroll
                for (int nf = 0; nf < 4; nf++) {
                    u32 h0 = bh[nf >> 1][(nf & 1) * 2], h1 = bh[nf >> 1][(nf & 1) * 2 + 1];
                    u32 l0 = bl[nf >> 1][(nf & 1) * 2], l1 = bl[nf >> 1][(nf & 1) * 2 + 1];
                    mma16816(acc[mf][nf], ah[mf], h0, h1);
                    mma16816(acc[mf][nf], ah[mf], l0, l1);
                    mma16816(acc[mf][nf], al[mf], h0, h1);
                }
        }
        __syncthreads();
    }
    int g = lane >> 2, tq = lane & 3;
    float* Cb = (MODE == 0) ? g_qkv : C;
#pragma unroll
    for (int nf = 0; nf < 4; nf++) {
        int col = col0 + warp_n * 32 + nf * 8 + 2 * tq;
        float b0v = bias[col], b1v = bias[col + 1];
#pragma unroll
        for (int mf = 0; mf < 4; mf++) {
            int rowA = row0 + warp_m * 64 + mf * 16 + g;
            *(float2*)&Cb[(size_t)rowA * ldn + col] = make_float2(acc[mf][nf][0] + b0v, acc[mf][nf][1] + b1v);
            *(float2*)&Cb[(size_t)(rowA + 8) * ldn + col] = make_float2(acc[mf][nf][2] + b0v, acc[mf][nf][3] + b1v);
        }
    }
}

__global__ __launch_bounds__(128) void attn_kernel() {
    extern __shared__ float sm[];  // 25 * 388
    int b = blockIdx.x, tid = threadIdx.x;
    const float* src = g_qkv + (size_t)b * 25 * 384;
    for (int i = tid; i < 2400; i += 128) {
        int row = i / 96, c = i - row * 96;
        *(float4*)&sm[row * QKS + c * 4] = *(const float4*)&src[row * 384 + c * 4];
    }
    __syncthreads();
    if (tid < 100) {
        int h = tid / 25, i = tid - h * 25;
        int rot = 2 * h;
        u64 qv[16];
#pragma unroll
        for (int q = 0; q < 8; q++) {
            int qq = (q + rot) & 7;
            ulonglong2 t = *(const ulonglong2*)&sm[i * QKS + h * 32 + qq * 4];
            qv[2 * q] = t.x; qv[2 * q + 1] = t.y;
        }
        const float scale = 0.17677669529663687f;
        const float* gb = g_bias + (((size_t)(b & 63) * 4 + h) * 25 + i) * 25;
        float s[25], m = -1e30f;
        for (int j = 0; j < 25; j++) {
            const float* kr = sm + j * QKS + 128 + h * 32;
            u64 acc = 0ull;
#pragma unroll
            for (int q = 0; q < 8; q++) {
                int qq = (q + rot) & 7;
                ulonglong2 t = *(const ulonglong2*)&kr[qq * 4];
                ffma2(acc, qv[2 * q], t.x);
                ffma2(acc, qv[2 * q + 1], t.y);
            }
            float sv = fsum2(acc) * scale + gb[j];
            s[j] = sv; m = fmaxf(m, sv);
        }
        float sum = 0.f;
        for (int j = 0; j < 25; j++) { s[j] = __expf(s[j] - m); sum += s[j]; }
        float inv = 1.f / sum;
        u64 o[16];
#pragma unroll
        for (int q = 0; q < 16; q++) o[q] = 0ull;
        for (int j = 0; j < 25; j++) {
            u64 pp = dup(s[j] * inv);
            const float* vr = sm + j * QKS + 256 + h * 32;
#pragma unroll
            for (int q = 0; q < 8; q++) {
                int qq = (q + rot) & 7;
                ulonglong2 t = *(const ulonglong2*)&vr[qq * 4];
                ffma2(o[2 * q], pp, t.x);
                ffma2(o[2 * q + 1], pp, t.y);
            }
        }
        float arr[32];
#pragma unroll
        for (int q = 0; q < 8; q++) {
            int qq = (q + rot) & 7;
            arr[qq * 4 + 0] = __uint_as_float((u32)o[2 * q]);
            arr[qq * 4 + 1] = __uint_as_float((u32)(o[2 * q] >> 32));
            arr[qq * 4 + 2] = __uint_as_float((u32)o[2 * q + 1]);
            arr[qq * 4 + 3] = __uint_as_float((u32)(o[2 * q + 1] >> 32));
        }
        size_t base = ((size_t)b * 25 + i) * 128 + h * 32;
#pragma unroll
        for (int g = 0; g < 4; g++) {
            BF8 hb, lb; split8(arr + g * 8, hb, lb);
            *(uint4*)&g_ao_hi[base + g * 8] = *(uint4*)&hb;
            *(uint4*)&g_ao_lo[base + g * 8] = *(uint4*)&lb;
        }
    }
}

extern "C" void kernel_launch(void* const* d_in, const int* in_sizes, int n_in,
                              void* d_out, int out_size) {
    const float* x          = (const float*)d_in[0];
    const float* mask       = (const float*)d_in[1];
    const int*   ids_keep   = (const int*)d_in[2];
    const float* qkv_w      = (const float*)d_in[3];
    const float* qkv_b      = (const float*)d_in[4];
    const float* proj_w     = (const float*)d_in[5];
    const float* proj_b     = (const float*)d_in[6];
    const float* bias_table = (const float*)d_in[7];
    const int*   rel_index  = (const int*)d_in[8];
    float* out = (float*)d_out;

    bias_kernel<<<64, 256>>>(mask, ids_keep, bias_table, rel_index);

    size_t gsm = 4 * 8192 * sizeof(__nv_bfloat16);  // 64 KB
    cudaFuncSetAttribute(gemm_kernel<0>, cudaFuncAttributeMaxDynamicSharedMemorySize, (int)gsm);
    cudaFuncSetAttribute(gemm_kernel<1>, cudaFuncAttributeMaxDynamicSharedMemorySize, (int)gsm);
    gemm_kernel<0><<<dim3(800, 3), 256, gsm>>>(x, qkv_w, qkv_b, nullptr, 384);

    size_t asm_sz = 25 * QKS * sizeof(float);
    cudaFuncSetAttribute(attn_kernel, cudaFuncAttributeMaxDynamicSharedMemorySize, (int)asm_sz);
    attn_kernel<<<4096, 128, asm_sz>>>();

    gemm_kernel<1><<<dim3(800, 1), 256, gsm>>>(nullptr, proj_w, proj_b, out, 128);
}